// round 1
// baseline (speedup 1.0000x reference)
#include <cuda_runtime.h>
#include <cstdint>
#include <math.h>

typedef unsigned long long ull;

#define BB 4096
#define LL 50
#define DD 64

constexpr int NTASK    = BB * 7;     // 6 tasks of 8 rows + 1 task of 2 rows per b
constexpr int THREADS1 = 512;
constexpr int NWARP    = 16;

// ---- smem layout (float offsets) ----
constexpr int O_W1Q = 0;          // gv_w1 quads  128x64 -> 8192
constexpr int O_W2Q = 8192;       // gv_w2        64x64  -> 4096
constexpr int O_W3Q = 12288;      // gv_w3                 4096
constexpr int O_A1Q = 16384;      // att_w1       128x64   8192
constexpr int O_A2Q = 24576;      // att_w2       64x64    4096
constexpr int O_W3V = 28672;      // att_w3 (64)
constexpr int O_BG1 = 28736;
constexpr int O_BG2 = 28800;
constexpr int O_BG3 = 28864;
constexpr int O_BA1 = 28928;
constexpr int O_BA2 = 28992;
constexpr int O_BA3 = 29056;      // 1 (padded to 64)
constexpr int O_XA  = 29120;      // 16 warps * 8 rows * 128
constexpr int O_XB  = O_XA + NWARP * 8 * 128;   // 16 warps * 8 rows * 64
constexpr int SMEM_FLOATS = O_XB + NWARP * 8 * 64;
constexpr int SMEM_BYTES  = SMEM_FLOATS * 4;    // 214784 B  (< 227KB)

// scratch (device-global, allowed per rules)
__device__ float g_scores[BB * LL];
__device__ float g_fjt[BB * LL * DD];

// ---- packed f32x2 helpers ----
__device__ __forceinline__ ull fma2(ull a, ull b, ull c) {
    ull d;
    asm("fma.rn.f32x2 %0, %1, %2, %3;" : "=l"(d) : "l"(a), "l"(b), "l"(c));
    return d;
}
__device__ __forceinline__ float2 unpack2(ull v) {
    float2 f;
    asm("mov.b64 {%0, %1}, %2;" : "=f"(f.x), "=f"(f.y) : "l"(v));
    return f;
}

// GEMV over R rows, lane computes output channels (lane, lane+32) as f32x2 pairs.
// Wq layout per entry e = k2*32+jj : (w[2k2][jj], w[2k2+1][jj], w[2k2][jj+32], w[2k2+1][jj+32])
template<int R>
__device__ __forceinline__ void gemm_pairs(
    const float* __restrict__ xs, int xstride,
    const ulonglong2* __restrict__ Wq, int K,
    ull initA, ull initB, ull* accA, ull* accB, int lane)
{
#pragma unroll
    for (int r = 0; r < R; r++) { accA[r] = initA; accB[r] = initB; }
#pragma unroll 4
    for (int k4 = 0; k4 < K / 4; k4++) {
        ulonglong2 w0 = Wq[(2 * k4) * 32 + lane];
        ulonglong2 w1 = Wq[(2 * k4 + 1) * 32 + lane];
#pragma unroll
        for (int r = 0; r < R; r++) {
            ulonglong2 xv = *reinterpret_cast<const ulonglong2*>(xs + r * xstride + 4 * k4);
            accA[r] = fma2(xv.x, w0.x, accA[r]);
            accB[r] = fma2(xv.x, w0.y, accB[r]);
            accA[r] = fma2(xv.y, w1.x, accA[r]);
            accB[r] = fma2(xv.y, w1.y, accB[r]);
        }
    }
}

__device__ __forceinline__ void load_quads(float* dstf, const float* __restrict__ w, int K, int tid) {
    float4* dst = reinterpret_cast<float4*>(dstf);
    int n = (K / 2) * 32;
    for (int e = tid; e < n; e += THREADS1) {
        int k2 = e >> 5, jj = e & 31;
        const float* p = w + (2 * k2) * 64;
        dst[e] = make_float4(p[jj], p[64 + jj], p[jj + 32], p[64 + jj + 32]);
    }
}

template<int R>
__device__ __forceinline__ void process_task(
    int b, int l0, float* sm, float* XA, float* XB, int lane,
    const int* __restrict__ nodes_v, const int* __restrict__ neigh_u,
    const int* __restrict__ neigh_r,
    const float* __restrict__ embed_u, const float* __restrict__ embed_i,
    const float* __restrict__ embed_r)
{
    const ulonglong2* W1Q = reinterpret_cast<const ulonglong2*>(sm + O_W1Q);
    const ulonglong2* W2Q = reinterpret_cast<const ulonglong2*>(sm + O_W2Q);
    const ulonglong2* W3Q = reinterpret_cast<const ulonglong2*>(sm + O_W3Q);
    const ulonglong2* A1Q = reinterpret_cast<const ulonglong2*>(sm + O_A1Q);
    const ulonglong2* A2Q = reinterpret_cast<const ulonglong2*>(sm + O_A2Q);

    __syncwarp();
    // ---- gather x = [embed_u[nu], embed_r[nr]] into XA rows, q into XB row 0 ----
#pragma unroll
    for (int r = 0; r < R; r++) {
        int l  = l0 + r;
        int nu = neigh_u[b * LL + l];
        int nr = neigh_r[b * LL + l];
        *reinterpret_cast<float2*>(&XA[r * 128 + 2 * lane]) =
            *reinterpret_cast<const float2*>(&embed_u[nu * 64 + 2 * lane]);
        *reinterpret_cast<float2*>(&XA[r * 128 + 64 + 2 * lane]) =
            *reinterpret_cast<const float2*>(&embed_r[nr * 64 + 2 * lane]);
    }
    int iv = nodes_v[b];
    *reinterpret_cast<float2*>(&XB[2 * lane]) =
        *reinterpret_cast<const float2*>(&embed_i[iv * 64 + 2 * lane]);
    __syncwarp();

    // ---- qc: q-half of att layer 1 (same for all rows of this b) ----
    ull qA, qB;
    {
        ull a[1], c[1];
        gemm_pairs<1>(XB, 64, A1Q + 1024, 64, 0ULL, 0ULL, a, c, lane);
        qA = a[0]; qB = c[0];
    }
    __syncwarp();

    ull aA[R], aB[R];

    // ---- gv layer 1: 128 -> 64, relu -> XB ----
    gemm_pairs<R>(XA, 128, W1Q, 128, 0ULL, 0ULL, aA, aB, lane);
    {
        float b0 = sm[O_BG1 + lane], b1 = sm[O_BG1 + lane + 32];
#pragma unroll
        for (int r = 0; r < R; r++) {
            float2 pa = unpack2(aA[r]), pb = unpack2(aB[r]);
            XB[r * 64 + lane]      = fmaxf(b0 + pa.x + pa.y, 0.f);
            XB[r * 64 + lane + 32] = fmaxf(b1 + pb.x + pb.y, 0.f);
        }
    }
    __syncwarp();

    // ---- gv layer 2: 64 -> 64, relu -> XA[:,0:64] ----
    gemm_pairs<R>(XB, 64, W2Q, 64, 0ULL, 0ULL, aA, aB, lane);
    {
        float b0 = sm[O_BG2 + lane], b1 = sm[O_BG2 + lane + 32];
#pragma unroll
        for (int r = 0; r < R; r++) {
            float2 pa = unpack2(aA[r]), pb = unpack2(aB[r]);
            XA[r * 128 + lane]      = fmaxf(b0 + pa.x + pa.y, 0.f);
            XA[r * 128 + lane + 32] = fmaxf(b1 + pb.x + pb.y, 0.f);
        }
    }
    __syncwarp();

    // ---- gv layer 3: 64 -> 64 (no relu) = fjt -> XB and global ----
    gemm_pairs<R>(XA, 128, W3Q, 64, 0ULL, 0ULL, aA, aB, lane);
    {
        float b0 = sm[O_BG3 + lane], b1 = sm[O_BG3 + lane + 32];
#pragma unroll
        for (int r = 0; r < R; r++) {
            float2 pa = unpack2(aA[r]), pb = unpack2(aB[r]);
            float f0 = b0 + pa.x + pa.y;
            float f1 = b1 + pb.x + pb.y;
            XB[r * 64 + lane]      = f0;
            XB[r * 64 + lane + 32] = f1;
            int row = (b * LL + l0 + r) * 64;
            g_fjt[row + lane]      = f0;
            g_fjt[row + lane + 32] = f1;
        }
    }
    __syncwarp();

    // ---- att layer 1: fjt-half + qc, relu -> XA[:,0:64] ----
    gemm_pairs<R>(XB, 64, A1Q, 64, qA, qB, aA, aB, lane);
    {
        float b0 = sm[O_BA1 + lane], b1 = sm[O_BA1 + lane + 32];
#pragma unroll
        for (int r = 0; r < R; r++) {
            float2 pa = unpack2(aA[r]), pb = unpack2(aB[r]);
            XA[r * 128 + lane]      = fmaxf(b0 + pa.x + pa.y, 0.f);
            XA[r * 128 + lane + 32] = fmaxf(b1 + pb.x + pb.y, 0.f);
        }
    }
    __syncwarp();

    // ---- att layer 2 + layer 3 (dot with w3) -> scores ----
    gemm_pairs<R>(XA, 128, A2Q, 64, 0ULL, 0ULL, aA, aB, lane);
    {
        float b0  = sm[O_BA2 + lane], b1 = sm[O_BA2 + lane + 32];
        float w3a = sm[O_W3V + lane], w3b = sm[O_W3V + lane + 32];
        float ba3 = sm[O_BA3];
#pragma unroll
        for (int r = 0; r < R; r++) {
            float2 pa = unpack2(aA[r]), pb = unpack2(aB[r]);
            float va = fmaxf(b0 + pa.x + pa.y, 0.f);
            float vb = fmaxf(b1 + pb.x + pb.y, 0.f);
            float p  = va * w3a + vb * w3b;
#pragma unroll
            for (int o = 16; o > 0; o >>= 1) p += __shfl_xor_sync(0xffffffffu, p, o);
            if (lane == 0) g_scores[b * LL + l0 + r] = p + ba3;
        }
    }
}

__global__ void __launch_bounds__(THREADS1, 1) mlp_kernel(
    const int* __restrict__ nodes_v, const int* __restrict__ neigh_u,
    const int* __restrict__ neigh_r,
    const float* __restrict__ embed_u, const float* __restrict__ embed_i,
    const float* __restrict__ embed_r,
    const float* __restrict__ gv_w1, const float* __restrict__ gv_b1,
    const float* __restrict__ gv_w2, const float* __restrict__ gv_b2,
    const float* __restrict__ gv_w3, const float* __restrict__ gv_b3,
    const float* __restrict__ att_w1, const float* __restrict__ att_b1,
    const float* __restrict__ att_w2, const float* __restrict__ att_b2,
    const float* __restrict__ att_w3, const float* __restrict__ att_b3)
{
    extern __shared__ float sm[];
    int tid = threadIdx.x;

    load_quads(sm + O_W1Q, gv_w1, 128, tid);
    load_quads(sm + O_W2Q, gv_w2, 64, tid);
    load_quads(sm + O_W3Q, gv_w3, 64, tid);
    load_quads(sm + O_A1Q, att_w1, 128, tid);
    load_quads(sm + O_A2Q, att_w2, 64, tid);
    if (tid < 64) {
        sm[O_W3V + tid] = att_w3[tid];
        sm[O_BG1 + tid] = gv_b1[tid];
        sm[O_BG2 + tid] = gv_b2[tid];
        sm[O_BG3 + tid] = gv_b3[tid];
        sm[O_BA1 + tid] = att_b1[tid];
        sm[O_BA2 + tid] = att_b2[tid];
    }
    if (tid == 0) sm[O_BA3] = att_b3[0];
    __syncthreads();

    int lane = tid & 31, warp = tid >> 5;
    float* XA = sm + O_XA + warp * 8 * 128;
    float* XB = sm + O_XB + warp * 8 * 64;

    for (int t = blockIdx.x * NWARP + warp; t < NTASK; t += gridDim.x * NWARP) {
        int b = t / 7, q = t - b * 7;
        if (q < 6)
            process_task<8>(b, q * 8, sm, XA, XB, lane,
                            nodes_v, neigh_u, neigh_r, embed_u, embed_i, embed_r);
        else
            process_task<2>(b, 48, sm, XA, XB, lane,
                            nodes_v, neigh_u, neigh_r, embed_u, embed_i, embed_r);
    }
}

// ---- kernel 2: softmax over neighbors, aggregate, combine MLP ----
__global__ void __launch_bounds__(64) combine_kernel(
    const int* __restrict__ nodes_v, const float* __restrict__ embed_i,
    const float* __restrict__ wr1_w, const float* __restrict__ wr1_b,
    const float* __restrict__ wr2_w, const float* __restrict__ wr2_b,
    float* __restrict__ out)
{
    __shared__ float sc[64];
    __shared__ float es[64];
    __shared__ float mu[64];
    __shared__ float zq[128];
    __shared__ float zz[64];

    int b = blockIdx.x;
    int tid = threadIdx.x;

    sc[tid] = (tid < LL) ? g_scores[b * LL + tid] : -1e30f;
    __syncthreads();

    float mx = -1e30f;
#pragma unroll 10
    for (int l = 0; l < LL; l++) mx = fmaxf(mx, sc[l]);
    es[tid] = (tid < LL) ? __expf(sc[tid] - mx) : 0.f;
    __syncthreads();

    float den = 0.f;
#pragma unroll 10
    for (int l = 0; l < LL; l++) den += es[l];
    mu[tid] = es[tid] / den;
    __syncthreads();

    // zj[d] = sum_l mu[l] * fjt[b,l,d] ; zq = [zj, qj]
    float acc = 0.f;
    const float* fb = g_fjt + (size_t)(b * LL) * 64 + tid;
#pragma unroll 10
    for (int l = 0; l < LL; l++) acc += mu[l] * fb[l * 64];
    zq[tid] = acc;
    int iv = nodes_v[b];
    zq[64 + tid] = embed_i[iv * 64 + tid];
    __syncthreads();

    float a1 = wr1_b[tid];
#pragma unroll 8
    for (int k = 0; k < 128; k++) a1 += zq[k] * wr1_w[k * 64 + tid];
    zz[tid] = fmaxf(a1, 0.f);
    __syncthreads();

    float a2 = wr2_b[tid];
#pragma unroll 8
    for (int k = 0; k < 64; k++) a2 += zz[k] * wr2_w[k * 64 + tid];
    out[b * 64 + tid] = fmaxf(a2, 0.f);
}

extern "C" void kernel_launch(void* const* d_in, const int* in_sizes, int n_in,
                              void* d_out, int out_size)
{
    const int*   nodes_v = (const int*)d_in[0];
    const int*   neigh_u = (const int*)d_in[1];
    const int*   neigh_r = (const int*)d_in[2];
    const float* embed_u = (const float*)d_in[3];
    const float* embed_i = (const float*)d_in[4];
    const float* embed_r = (const float*)d_in[5];
    const float* gv_w1  = (const float*)d_in[6];
    const float* gv_b1  = (const float*)d_in[7];
    const float* gv_w2  = (const float*)d_in[8];
    const float* gv_b2  = (const float*)d_in[9];
    const float* gv_w3  = (const float*)d_in[10];
    const float* gv_b3  = (const float*)d_in[11];
    const float* att_w1 = (const float*)d_in[12];
    const float* att_b1 = (const float*)d_in[13];
    const float* att_w2 = (const float*)d_in[14];
    const float* att_b2 = (const float*)d_in[15];
    const float* att_w3 = (const float*)d_in[16];
    const float* att_b3 = (const float*)d_in[17];
    const float* wr1_w  = (const float*)d_in[18];
    const float* wr1_b  = (const float*)d_in[19];
    const float* wr2_w  = (const float*)d_in[20];
    const float* wr2_b  = (const float*)d_in[21];
    float* out = (float*)d_out;

    cudaFuncSetAttribute(mlp_kernel, cudaFuncAttributeMaxDynamicSharedMemorySize, SMEM_BYTES);

    int smCount = 148;
    cudaDeviceGetAttribute(&smCount, cudaDevAttrMultiProcessorCount, 0);

    mlp_kernel<<<smCount, THREADS1, SMEM_BYTES>>>(
        nodes_v, neigh_u, neigh_r, embed_u, embed_i, embed_r,
        gv_w1, gv_b1, gv_w2, gv_b2, gv_w3, gv_b3,
        att_w1, att_b1, att_w2, att_b2, att_w3, att_b3);

    combine_kernel<<<BB, 64>>>(nodes_v, embed_i, wr1_w, wr1_b, wr2_w, wr2_b, out);
}

// round 2
// speedup vs baseline: 1.1428x; 1.1428x over previous
#include <cuda_runtime.h>
#include <cstdint>
#include <math.h>

typedef unsigned long long ull;

#define BB 4096
#define LL 50
#define DD 64

constexpr int NTASK    = BB * 7;     // 6 tasks of 8 rows + 1 task of 2 rows per b
constexpr int THREADS1 = 512;
constexpr int NWARP    = 16;

// ---- smem layout (float offsets) ----
constexpr int O_W1Q = 0;              // gv_w1 (pt half only, K=64) quads -> 4096
constexpr int O_W2Q = 4096;           // gv_w2  -> 4096
constexpr int O_W3Q = 8192;           // gv_w3  -> 4096
constexpr int O_A1Q = 12288;          // att_w1 full K=128 -> 8192
constexpr int O_A2Q = 20480;          // att_w2 -> 4096
constexpr int O_W3V = 24576;          // att_w3 (64)
constexpr int O_BG1 = 24640;
constexpr int O_BG2 = 24704;
constexpr int O_BG3 = 24768;
constexpr int O_BA1 = 24832;
constexpr int O_BA2 = 24896;
constexpr int O_BA3 = 24960;          // 1 (padded to 64)
constexpr int O_EP  = 25024;          // er_proj[5][64] = 320
constexpr int O_XA  = 25344;          // 16 warps * 8 rows * 64
constexpr int O_XB  = O_XA + NWARP * 8 * 64;
constexpr int SMEM_FLOATS = O_XB + NWARP * 8 * 64;
constexpr int SMEM_BYTES  = SMEM_FLOATS * 4;   // 166912 B

// scratch (device-global, allowed per rules)
__device__ float g_scores[BB * LL];
__device__ float g_fjt[BB * LL * DD];

// ---- packed f32x2 helpers ----
__device__ __forceinline__ ull fma2(ull a, ull b, ull c) {
    ull d;
    asm("fma.rn.f32x2 %0, %1, %2, %3;" : "=l"(d) : "l"(a), "l"(b), "l"(c));
    return d;
}
__device__ __forceinline__ float2 unpack2(ull v) {
    float2 f;
    asm("mov.b64 {%0, %1}, %2;" : "=f"(f.x), "=f"(f.y) : "l"(v));
    return f;
}
__device__ __forceinline__ ull pack2(float x, float y) {
    ull v;
    asm("mov.b64 %0, {%1, %2};" : "=l"(v) : "f"(x), "f"(y));
    return v;
}

// Accumulating GEMV over R rows; lane computes output channels (lane, lane+32)
// as f32x2 (even-k, odd-k) partial pairs. Caller pre-initializes accA/accB.
// Wq layout per entry e = k2*32+jj : (w[2k2][jj], w[2k2+1][jj], w[2k2][jj+32], w[2k2+1][jj+32])
template<int R, int K, int XS>
__device__ __forceinline__ void gemm_acc(
    const float* __restrict__ xs, const ulonglong2* __restrict__ Wq,
    ull* accA, ull* accB, int lane)
{
#pragma unroll 4
    for (int k4 = 0; k4 < K / 4; k4++) {
        ulonglong2 w0 = Wq[(2 * k4) * 32 + lane];
        ulonglong2 w1 = Wq[(2 * k4 + 1) * 32 + lane];
#pragma unroll
        for (int r = 0; r < R; r++) {
            ulonglong2 xv = *reinterpret_cast<const ulonglong2*>(xs + r * XS + 4 * k4);
            accA[r] = fma2(xv.x, w0.x, accA[r]);
            accB[r] = fma2(xv.x, w0.y, accB[r]);
            accA[r] = fma2(xv.y, w1.x, accA[r]);
            accB[r] = fma2(xv.y, w1.y, accB[r]);
        }
    }
}

__device__ __forceinline__ void load_quads(float* dstf, const float* __restrict__ w, int K, int tid) {
    float4* dst = reinterpret_cast<float4*>(dstf);
    int n = (K / 2) * 32;
    for (int e = tid; e < n; e += THREADS1) {
        int k2 = e >> 5, jj = e & 31;
        const float* p = w + (2 * k2) * 64;
        dst[e] = make_float4(p[jj], p[64 + jj], p[jj + 32], p[64 + jj + 32]);
    }
}

template<int R>
__device__ __forceinline__ void process_task(
    int b, int l0, float* sm, float* XA, float* XB, int lane,
    const int* __restrict__ nodes_v, const int* __restrict__ neigh_u,
    const int* __restrict__ neigh_r,
    const float* __restrict__ embed_u, const float* __restrict__ embed_i)
{
    const ulonglong2* W1Q = reinterpret_cast<const ulonglong2*>(sm + O_W1Q);
    const ulonglong2* W2Q = reinterpret_cast<const ulonglong2*>(sm + O_W2Q);
    const ulonglong2* W3Q = reinterpret_cast<const ulonglong2*>(sm + O_W3Q);
    const ulonglong2* A1Q = reinterpret_cast<const ulonglong2*>(sm + O_A1Q);
    const ulonglong2* A2Q = reinterpret_cast<const ulonglong2*>(sm + O_A2Q);

    int nrs[R];

    __syncwarp();
    // ---- gather x = embed_u[nu] into XA rows, read nr indices, q into XB row 0 ----
#pragma unroll
    for (int r = 0; r < R; r++) {
        int l  = l0 + r;
        int nu = neigh_u[b * LL + l];
        nrs[r] = neigh_r[b * LL + l];
        *reinterpret_cast<float2*>(&XA[r * 64 + 2 * lane]) =
            *reinterpret_cast<const float2*>(&embed_u[nu * 64 + 2 * lane]);
    }
    int iv = nodes_v[b];
    *reinterpret_cast<float2*>(&XB[2 * lane]) =
        *reinterpret_cast<const float2*>(&embed_i[iv * 64 + 2 * lane]);
    __syncwarp();

    // ---- qc: q-half of att layer 1 (same for all rows of this b) ----
    ull qA, qB;
    {
        ull a[1] = {0ULL}, c[1] = {0ULL};
        gemm_acc<1, 64, 64>(XB, A1Q + 1024, a, c, lane);
        qA = a[0]; qB = c[0];
    }
    __syncwarp();

    ull aA[R], aB[R];

    // ---- gv layer 1: pt-half (K=64) + er_proj[nr] init, relu -> XB ----
#pragma unroll
    for (int r = 0; r < R; r++) {
        const float* ep = sm + O_EP + nrs[r] * 64;
        aA[r] = pack2(ep[lane], 0.f);
        aB[r] = pack2(ep[lane + 32], 0.f);
    }
    gemm_acc<R, 64, 64>(XA, W1Q, aA, aB, lane);
    {
        float b0 = sm[O_BG1 + lane], b1 = sm[O_BG1 + lane + 32];
#pragma unroll
        for (int r = 0; r < R; r++) {
            float2 pa = unpack2(aA[r]), pb = unpack2(aB[r]);
            XB[r * 64 + lane]      = fmaxf(b0 + pa.x + pa.y, 0.f);
            XB[r * 64 + lane + 32] = fmaxf(b1 + pb.x + pb.y, 0.f);
        }
    }
    __syncwarp();

    // ---- gv layer 2: 64 -> 64, relu -> XA ----
#pragma unroll
    for (int r = 0; r < R; r++) { aA[r] = 0ULL; aB[r] = 0ULL; }
    gemm_acc<R, 64, 64>(XB, W2Q, aA, aB, lane);
    {
        float b0 = sm[O_BG2 + lane], b1 = sm[O_BG2 + lane + 32];
#pragma unroll
        for (int r = 0; r < R; r++) {
            float2 pa = unpack2(aA[r]), pb = unpack2(aB[r]);
            XA[r * 64 + lane]      = fmaxf(b0 + pa.x + pa.y, 0.f);
            XA[r * 64 + lane + 32] = fmaxf(b1 + pb.x + pb.y, 0.f);
        }
    }
    __syncwarp();

    // ---- gv layer 3: 64 -> 64 (no relu) = fjt -> XB and global ----
#pragma unroll
    for (int r = 0; r < R; r++) { aA[r] = 0ULL; aB[r] = 0ULL; }
    gemm_acc<R, 64, 64>(XA, W3Q, aA, aB, lane);
    {
        float b0 = sm[O_BG3 + lane], b1 = sm[O_BG3 + lane + 32];
#pragma unroll
        for (int r = 0; r < R; r++) {
            float2 pa = unpack2(aA[r]), pb = unpack2(aB[r]);
            float f0 = b0 + pa.x + pa.y;
            float f1 = b1 + pb.x + pb.y;
            XB[r * 64 + lane]      = f0;
            XB[r * 64 + lane + 32] = f1;
            int row = (b * LL + l0 + r) * 64;
            g_fjt[row + lane]      = f0;
            g_fjt[row + lane + 32] = f1;
        }
    }
    __syncwarp();

    // ---- att layer 1: fjt-half (K=64) + hoisted qc init, relu -> XA ----
#pragma unroll
    for (int r = 0; r < R; r++) { aA[r] = qA; aB[r] = qB; }
    gemm_acc<R, 64, 64>(XB, A1Q, aA, aB, lane);
    {
        float b0 = sm[O_BA1 + lane], b1 = sm[O_BA1 + lane + 32];
#pragma unroll
        for (int r = 0; r < R; r++) {
            float2 pa = unpack2(aA[r]), pb = unpack2(aB[r]);
            XA[r * 64 + lane]      = fmaxf(b0 + pa.x + pa.y, 0.f);
            XA[r * 64 + lane + 32] = fmaxf(b1 + pb.x + pb.y, 0.f);
        }
    }
    __syncwarp();

    // ---- att layer 2 + layer 3 (dot with w3) -> scores ----
#pragma unroll
    for (int r = 0; r < R; r++) { aA[r] = 0ULL; aB[r] = 0ULL; }
    gemm_acc<R, 64, 64>(XA, A2Q, aA, aB, lane);
    {
        float b0  = sm[O_BA2 + lane], b1 = sm[O_BA2 + lane + 32];
        float w3a = sm[O_W3V + lane], w3b = sm[O_W3V + lane + 32];
        float ba3 = sm[O_BA3];
#pragma unroll
        for (int r = 0; r < R; r++) {
            float2 pa = unpack2(aA[r]), pb = unpack2(aB[r]);
            float va = fmaxf(b0 + pa.x + pa.y, 0.f);
            float vb = fmaxf(b1 + pb.x + pb.y, 0.f);
            float p  = va * w3a + vb * w3b;
#pragma unroll
            for (int o = 16; o > 0; o >>= 1) p += __shfl_xor_sync(0xffffffffu, p, o);
            if (lane == 0) g_scores[b * LL + l0 + r] = p + ba3;
        }
    }
}

__global__ void __launch_bounds__(THREADS1, 1) mlp_kernel(
    const int* __restrict__ nodes_v, const int* __restrict__ neigh_u,
    const int* __restrict__ neigh_r,
    const float* __restrict__ embed_u, const float* __restrict__ embed_i,
    const float* __restrict__ embed_r,
    const float* __restrict__ gv_w1, const float* __restrict__ gv_b1,
    const float* __restrict__ gv_w2, const float* __restrict__ gv_b2,
    const float* __restrict__ gv_w3, const float* __restrict__ gv_b3,
    const float* __restrict__ att_w1, const float* __restrict__ att_b1,
    const float* __restrict__ att_w2, const float* __restrict__ att_b2,
    const float* __restrict__ att_w3, const float* __restrict__ att_b3)
{
    extern __shared__ float sm[];
    int tid = threadIdx.x;

    load_quads(sm + O_W1Q, gv_w1, 64, tid);     // pt half of gv_w1 (rows 0..63)
    load_quads(sm + O_W2Q, gv_w2, 64, tid);
    load_quads(sm + O_W3Q, gv_w3, 64, tid);
    load_quads(sm + O_A1Q, att_w1, 128, tid);   // full (lower=fjt half, upper=q half)
    load_quads(sm + O_A2Q, att_w2, 64, tid);
    if (tid < 64) {
        sm[O_W3V + tid] = att_w3[tid];
        sm[O_BG1 + tid] = gv_b1[tid];
        sm[O_BG2 + tid] = gv_b2[tid];
        sm[O_BG3 + tid] = gv_b3[tid];
        sm[O_BA1 + tid] = att_b1[tid];
        sm[O_BA2 + tid] = att_b2[tid];
    }
    if (tid == 0) sm[O_BA3] = att_b3[0];
    // er_proj[r][j] = sum_k embed_r[r][k] * gv_w1[64+k][j]   (NR=5, D=64)
    if (tid < 5 * 64) {
        int r = tid >> 6, j = tid & 63;
        float s = 0.f;
#pragma unroll 8
        for (int k = 0; k < 64; k++)
            s += embed_r[r * 64 + k] * gv_w1[(64 + k) * 64 + j];
        sm[O_EP + tid] = s;
    }
    __syncthreads();

    int lane = tid & 31, warp = tid >> 5;
    float* XA = sm + O_XA + warp * 8 * 64;
    float* XB = sm + O_XB + warp * 8 * 64;

    for (int t = blockIdx.x * NWARP + warp; t < NTASK; t += gridDim.x * NWARP) {
        int b = t / 7, q = t - b * 7;
        if (q < 6)
            process_task<8>(b, q * 8, sm, XA, XB, lane,
                            nodes_v, neigh_u, neigh_r, embed_u, embed_i);
        else
            process_task<2>(b, 48, sm, XA, XB, lane,
                            nodes_v, neigh_u, neigh_r, embed_u, embed_i);
    }
}

// ---- kernel 2: softmax over neighbors, aggregate, combine MLP ----
__global__ void __launch_bounds__(64) combine_kernel(
    const int* __restrict__ nodes_v, const float* __restrict__ embed_i,
    const float* __restrict__ wr1_w, const float* __restrict__ wr1_b,
    const float* __restrict__ wr2_w, const float* __restrict__ wr2_b,
    float* __restrict__ out)
{
    __shared__ float sc[64];
    __shared__ float es[64];
    __shared__ float mu[64];
    __shared__ float zq[128];
    __shared__ float zz[64];

    int b = blockIdx.x;
    int tid = threadIdx.x;

    sc[tid] = (tid < LL) ? g_scores[b * LL + tid] : -1e30f;
    __syncthreads();

    float mx = -1e30f;
#pragma unroll 10
    for (int l = 0; l < LL; l++) mx = fmaxf(mx, sc[l]);
    es[tid] = (tid < LL) ? __expf(sc[tid] - mx) : 0.f;
    __syncthreads();

    float den = 0.f;
#pragma unroll 10
    for (int l = 0; l < LL; l++) den += es[l];
    mu[tid] = es[tid] / den;
    __syncthreads();

    // zj[d] = sum_l mu[l] * fjt[b,l,d] ; zq = [zj, qj]
    float acc = 0.f;
    const float* fb = g_fjt + (size_t)(b * LL) * 64 + tid;
#pragma unroll 10
    for (int l = 0; l < LL; l++) acc += mu[l] * fb[l * 64];
    zq[tid] = acc;
    int iv = nodes_v[b];
    zq[64 + tid] = embed_i[iv * 64 + tid];
    __syncthreads();

    float a1 = wr1_b[tid];
#pragma unroll 8
    for (int k = 0; k < 128; k++) a1 += zq[k] * wr1_w[k * 64 + tid];
    zz[tid] = fmaxf(a1, 0.f);
    __syncthreads();

    float a2 = wr2_b[tid];
#pragma unroll 8
    for (int k = 0; k < 64; k++) a2 += zz[k] * wr2_w[k * 64 + tid];
    out[b * 64 + tid] = fmaxf(a2, 0.f);
}

extern "C" void kernel_launch(void* const* d_in, const int* in_sizes, int n_in,
                              void* d_out, int out_size)
{
    const int*   nodes_v = (const int*)d_in[0];
    const int*   neigh_u = (const int*)d_in[1];
    const int*   neigh_r = (const int*)d_in[2];
    const float* embed_u = (const float*)d_in[3];
    const float* embed_i = (const float*)d_in[4];
    const float* embed_r = (const float*)d_in[5];
    const float* gv_w1  = (const float*)d_in[6];
    const float* gv_b1  = (const float*)d_in[7];
    const float* gv_w2  = (const float*)d_in[8];
    const float* gv_b2  = (const float*)d_in[9];
    const float* gv_w3  = (const float*)d_in[10];
    const float* gv_b3  = (const float*)d_in[11];
    const float* att_w1 = (const float*)d_in[12];
    const float* att_b1 = (const float*)d_in[13];
    const float* att_w2 = (const float*)d_in[14];
    const float* att_b2 = (const float*)d_in[15];
    const float* att_w3 = (const float*)d_in[16];
    const float* att_b3 = (const float*)d_in[17];
    const float* wr1_w  = (const float*)d_in[18];
    const float* wr1_b  = (const float*)d_in[19];
    const float* wr2_w  = (const float*)d_in[20];
    const float* wr2_b  = (const float*)d_in[21];
    float* out = (float*)d_out;

    cudaFuncSetAttribute(mlp_kernel, cudaFuncAttributeMaxDynamicSharedMemorySize, SMEM_BYTES);

    int smCount = 148;
    cudaDeviceGetAttribute(&smCount, cudaDevAttrMultiProcessorCount, 0);

    mlp_kernel<<<smCount, THREADS1, SMEM_BYTES>>>(
        nodes_v, neigh_u, neigh_r, embed_u, embed_i, embed_r,
        gv_w1, gv_b1, gv_w2, gv_b2, gv_w3, gv_b3,
        att_w1, att_b1, att_w2, att_b2, att_w3, att_b3);

    combine_kernel<<<BB, 64>>>(nodes_v, embed_i, wr1_w, wr1_b, wr2_w, wr2_b, out);
}